// round 7
// baseline (speedup 1.0000x reference)
#include <cuda_runtime.h>
#include <cuda_fp16.h>
#include <cstdint>

// Problem constants
#define B_    2
#define S_    512
#define D_    512
#define MTOK  1024          // B*S tokens
#define NTOT  1536          // w1 | w2 | w3
#define EPS_  1e-5f

// Static device scratch
__device__ float  g_P[MTOK * NTOT];     // 6 MB projections
__device__ __half g_A0[MTOK * D_];      // X hi split
__device__ __half g_A1[MTOK * D_];      // X lo split
__device__ __half g_B0[NTOT * D_];      // W concat hi split
__device__ __half g_B1[NTOT * D_];      // W concat lo split

// ---------------------------------------------------------------------------
// Kernel 0: split fp32 -> fp16 hi/lo. 16 floats/thread for deep MLP.
// ---------------------------------------------------------------------------
#define XFL   (MTOK * D_)               // 524288 floats in X
#define TOT16 ((MTOK + NTOT) * D_ / 16) // 81920 groups of 16

__global__ __launch_bounds__(256) void split_kernel(
    const float* __restrict__ X,
    const float* __restrict__ Win,
    const float* __restrict__ Wout,
    const float* __restrict__ Wb)
{
    const int g = blockIdx.x * 256 + threadIdx.x;
    if (g >= TOT16) return;

    #pragma unroll
    for (int h = 0; h < 2; ++h) {
        const int q = g * 16 + h * 8;
        const float* src;
        __half *d0, *d1;
        if (q < XFL) {
            src = X + q;
            d0 = g_A0 + q;  d1 = g_A1 + q;
        } else {
            const int wq = q - XFL;
            const int n  = wq >> 9;
            const int k  = wq & (D_ - 1);
            src = (n < D_ ? Win + n * D_
                          : (n < 2 * D_ ? Wout + (n - D_) * D_
                                        : Wb + (n - 2 * D_) * D_)) + k;
            d0 = g_B0 + wq;  d1 = g_B1 + wq;
        }
        const float4 v0 = reinterpret_cast<const float4*>(src)[0];
        const float4 v1 = reinterpret_cast<const float4*>(src)[1];
        float f[8] = {v0.x, v0.y, v0.z, v0.w, v1.x, v1.y, v1.z, v1.w};
        __half hi[8], lo[8];
        #pragma unroll
        for (int i = 0; i < 8; ++i) {
            hi[i] = __float2half_rn(f[i]);
            lo[i] = __float2half_rn(f[i] - __half2float(hi[i]));
        }
        uint4 sh, sl;
        sh.x = *(uint32_t*)&hi[0]; sh.y = *(uint32_t*)&hi[2];
        sh.z = *(uint32_t*)&hi[4]; sh.w = *(uint32_t*)&hi[6];
        sl.x = *(uint32_t*)&lo[0]; sl.y = *(uint32_t*)&lo[2];
        sl.z = *(uint32_t*)&lo[4]; sl.w = *(uint32_t*)&lo[6];
        *reinterpret_cast<uint4*>(d0) = sh;
        *reinterpret_cast<uint4*>(d1) = sl;
    }
}

// ---------------------------------------------------------------------------
// Kernel 1: GEMM P[m,n] = sum_k X[m,k]*W[n,k], fp16 3-pass split.
// hi*hi pass -> fp32 accumulators; hi*lo + lo*hi -> shared fp16 accumulators
// (corrections are ~2^-12 of the result; fp16 accumulation error ~3e-6 rel).
// BM=128 BN=96 BK=32, grid 8x16 = 128 CTAs (one uniform wave).
// ---------------------------------------------------------------------------
#define BM 128
#define BN 96
#define BK 32
#define KP 40
#define A_OFF   0
#define A1_OFF  (BM * KP)
#define B_OFF   (2 * BM * KP)
#define B1_OFF  (2 * BM * KP + BN * KP)
#define STAGE_H (2 * BM * KP + 2 * BN * KP)  // 17920 halves
#define GSMEM   (2 * STAGE_H * 2)            // 71680 B

__device__ __forceinline__ void cp16(uint32_t smem, const void* gmem) {
    asm volatile("cp.async.cg.shared.global [%0], [%1], 16;\n"
                 :: "r"(smem), "l"(gmem));
}

__device__ __forceinline__ void mma_f32acc(float* c,
    uint32_t a0, uint32_t a1, uint32_t a2, uint32_t a3,
    uint32_t b0, uint32_t b1)
{
    asm volatile(
        "mma.sync.aligned.m16n8k16.row.col.f32.f16.f16.f32 "
        "{%0,%1,%2,%3}, {%4,%5,%6,%7}, {%8,%9}, {%0,%1,%2,%3};"
        : "+f"(c[0]), "+f"(c[1]), "+f"(c[2]), "+f"(c[3])
        : "r"(a0), "r"(a1), "r"(a2), "r"(a3), "r"(b0), "r"(b1));
}

__device__ __forceinline__ void mma_f16acc(uint32_t* c,
    uint32_t a0, uint32_t a1, uint32_t a2, uint32_t a3,
    uint32_t b0, uint32_t b1)
{
    asm volatile(
        "mma.sync.aligned.m16n8k16.row.col.f16.f16.f16.f16 "
        "{%0,%1}, {%2,%3,%4,%5}, {%6,%7}, {%0,%1};"
        : "+r"(c[0]), "+r"(c[1])
        : "r"(a0), "r"(a1), "r"(a2), "r"(a3), "r"(b0), "r"(b1));
}

__global__ __launch_bounds__(256, 1) void gemm3_f16()
{
    extern __shared__ __half sm[];

    const int tid   = threadIdx.x;
    const int lane  = tid & 31;
    const int wid   = tid >> 5;
    const int warpM = wid >> 1;         // 0..3
    const int warpN = wid & 1;          // 0..1
    const int gID   = lane >> 2;        // 0..7
    const int tIG   = lane & 3;         // 0..3
    const int m0    = blockIdx.x * BM;
    const int n0    = blockIdx.y * BN;

    const uint32_t sbase = (uint32_t)__cvta_generic_to_shared(sm);

    float acc[2][6][4];
    uint32_t hacc[2][6][2];             // fp16x2 correction accumulators
    #pragma unroll
    for (int i = 0; i < 2; i++)
        #pragma unroll
        for (int j = 0; j < 6; j++) {
            #pragma unroll
            for (int q = 0; q < 4; q++) acc[i][j][q] = 0.f;
            hacc[i][j][0] = 0u; hacc[i][j][1] = 0u;
        }

    auto issue = [&](int t, int stg) {
        const int k0 = t * BK;
        const uint32_t st = sbase + (uint32_t)(stg * STAGE_H) * 2u;
        #pragma unroll
        for (int it = 0; it < 2; ++it) {
            const int c = tid + it * 256;
            const int r = c >> 2, qd = c & 3;
            const uint32_t so = (uint32_t)(r * KP + qd * 8) * 2u;
            cp16(st + A_OFF * 2u + so,  g_A0 + (m0 + r) * D_ + k0 + qd * 8);
            cp16(st + A1_OFF * 2u + so, g_A1 + (m0 + r) * D_ + k0 + qd * 8);
        }
        #pragma unroll
        for (int c = tid; c < 384; c += 256) {
            const int r = c >> 2, qd = c & 3;
            const uint32_t so = (uint32_t)(r * KP + qd * 8) * 2u;
            cp16(st + B_OFF * 2u + so,  g_B0 + (n0 + r) * D_ + k0 + qd * 8);
            cp16(st + B1_OFF * 2u + so, g_B1 + (n0 + r) * D_ + k0 + qd * 8);
        }
        asm volatile("cp.async.commit_group;");
    };

    auto compute = [&](int stg) {
        const __half* Ah = sm + stg * STAGE_H + A_OFF;
        const __half* Al = sm + stg * STAGE_H + A1_OFF;
        const __half* Bh = sm + stg * STAGE_H + B_OFF;
        const __half* Bl = sm + stg * STAGE_H + B1_OFF;
        #pragma unroll
        for (int kk = 0; kk < BK; kk += 16) {
            uint32_t ah[2][4], al[2][4], bh[6][2], bl[6][2];
            #pragma unroll
            for (int i = 0; i < 2; ++i) {
                const int r = warpM * 32 + i * 16 + gID;
                const int c = kk + 2 * tIG;
                ah[i][0] = *(const uint32_t*)&Ah[r * KP + c];
                ah[i][1] = *(const uint32_t*)&Ah[(r + 8) * KP + c];
                ah[i][2] = *(const uint32_t*)&Ah[r * KP + c + 8];
                ah[i][3] = *(const uint32_t*)&Ah[(r + 8) * KP + c + 8];
                al[i][0] = *(const uint32_t*)&Al[r * KP + c];
                al[i][1] = *(const uint32_t*)&Al[(r + 8) * KP + c];
                al[i][2] = *(const uint32_t*)&Al[r * KP + c + 8];
                al[i][3] = *(const uint32_t*)&Al[(r + 8) * KP + c + 8];
            }
            #pragma unroll
            for (int j = 0; j < 6; ++j) {
                const int n = warpN * 48 + j * 8 + gID;
                const int c = kk + 2 * tIG;
                bh[j][0] = *(const uint32_t*)&Bh[n * KP + c];
                bh[j][1] = *(const uint32_t*)&Bh[n * KP + c + 8];
                bl[j][0] = *(const uint32_t*)&Bl[n * KP + c];
                bl[j][1] = *(const uint32_t*)&Bl[n * KP + c + 8];
            }
            // Correction passes -> fp16 accumulators
            #pragma unroll
            for (int i = 0; i < 2; ++i)
                #pragma unroll
                for (int j = 0; j < 6; ++j)
                    mma_f16acc(hacc[i][j], ah[i][0], ah[i][1], ah[i][2], ah[i][3],
                               bl[j][0], bl[j][1]);                 // hi*lo
            #pragma unroll
            for (int i = 0; i < 2; ++i)
                #pragma unroll
                for (int j = 0; j < 6; ++j)
                    mma_f16acc(hacc[i][j], al[i][0], al[i][1], al[i][2], al[i][3],
                               bh[j][0], bh[j][1]);                 // lo*hi
            // Main pass -> fp32 accumulators
            #pragma unroll
            for (int i = 0; i < 2; ++i)
                #pragma unroll
                for (int j = 0; j < 6; ++j)
                    mma_f32acc(acc[i][j], ah[i][0], ah[i][1], ah[i][2], ah[i][3],
                               bh[j][0], bh[j][1]);                 // hi*hi
        }
    };

    constexpr int T = D_ / BK;   // 16
    issue(0, 0);
    #pragma unroll 1
    for (int t = 0; t < T; ++t) {
        if (t + 1 < T) {
            issue(t + 1, (t + 1) & 1);
            asm volatile("cp.async.wait_group 1;");
        } else {
            asm volatile("cp.async.wait_group 0;");
        }
        __syncthreads();
        compute(t & 1);
        __syncthreads();
    }

    // Epilogue: fold fp16 corrections into fp32 acc, store float2
    #pragma unroll
    for (int i = 0; i < 2; ++i) {
        const int r = m0 + warpM * 32 + i * 16 + gID;
        #pragma unroll
        for (int j = 0; j < 6; ++j) {
            const float2 c0 = __half22float2(*(__half2*)&hacc[i][j][0]);
            const float2 c1 = __half22float2(*(__half2*)&hacc[i][j][1]);
            const int c = n0 + warpN * 48 + j * 8 + 2 * tIG;
            *reinterpret_cast<float2*>(&g_P[r * NTOT + c]) =
                make_float2(acc[i][j][0] + c0.x, acc[i][j][1] + c0.y);
            *reinterpret_cast<float2*>(&g_P[(r + 8) * NTOT + c]) =
                make_float2(acc[i][j][2] + c1.x, acc[i][j][3] + c1.y);
        }
    }
}

// ---------------------------------------------------------------------------
// Kernel 2: per-token closed-form epilogue (rank-1 LN collapse).
// ---------------------------------------------------------------------------
__global__ __launch_bounds__(128) void finalize_kernel(
    const float* __restrict__ X, float* __restrict__ Y)
{
    __shared__ float red[6][4];
    const int m   = blockIdx.x;
    const int tid = threadIdx.x;
    const float* x = X + m * D_;
    const float* p = g_P + m * NTOT;   // w1 | w2 | w3

    const float4 a4  = *reinterpret_cast<const float4*>(&p[4 * tid]);
    const float4 x4  = *reinterpret_cast<const float4*>(&x[4 * tid]);
    const float4 c4  = *reinterpret_cast<const float4*>(&p[2 * D_ + 4 * tid]);

    float sw1  = (a4.x + a4.y) + (a4.z + a4.w);
    float sw1q = (a4.x * a4.x + a4.y * a4.y) + (a4.z * a4.z + a4.w * a4.w);
    float sx   = (x4.x + x4.y) + (x4.z + x4.w);
    float sw1x = (a4.x * x4.x + a4.y * x4.y) + (a4.z * x4.z + a4.w * x4.w);
    float sw3  = (c4.x + c4.y) + (c4.z + c4.w);
    float sw3q = (c4.x * c4.x + c4.y * c4.y) + (c4.z * c4.z + c4.w * c4.w);

    #pragma unroll
    for (int o = 16; o; o >>= 1) {
        sw1  += __shfl_xor_sync(0xffffffffu, sw1,  o);
        sw1q += __shfl_xor_sync(0xffffffffu, sw1q, o);
        sx   += __shfl_xor_sync(0xffffffffu, sx,   o);
        sw1x += __shfl_xor_sync(0xffffffffu, sw1x, o);
        sw3  += __shfl_xor_sync(0xffffffffu, sw3,  o);
        sw3q += __shfl_xor_sync(0xffffffffu, sw3q, o);
    }
    const int warp = tid >> 5, lane = tid & 31;
    if (lane == 0) {
        red[0][warp] = sw1;  red[1][warp] = sw1q; red[2][warp] = sx;
        red[3][warp] = sw1x; red[4][warp] = sw3;  red[5][warp] = sw3q;
    }
    __syncthreads();

    float r[6];
    #pragma unroll
    for (int j = 0; j < 6; j++)
        r[j] = (red[j][0] + red[j][1]) + (red[j][2] + red[j][3]);

    const float invD = 1.0f / (float)D_;
    const float mu1  = r[0] * invD;
    const float var1 = fmaxf(r[1] * invD - mu1 * mu1, 0.f);
    const float s    = r[3] - mu1 * r[2];
    const float mu3  = r[4] * invD;
    const float var3 = fmaxf(r[5] * invD - mu3 * mu3, 0.f);
    const float inv3 = rsqrtf(var3 + EPS_);

    const float4 v4 = *reinterpret_cast<const float4*>(&p[D_ + 4 * tid]);
    float4 out;
    out.x = v4.x * s * rsqrtf(v4.x * v4.x * var1 + EPS_) + (c4.x - mu3) * inv3;
    out.y = v4.y * s * rsqrtf(v4.y * v4.y * var1 + EPS_) + (c4.y - mu3) * inv3;
    out.z = v4.z * s * rsqrtf(v4.z * v4.z * var1 + EPS_) + (c4.z - mu3) * inv3;
    out.w = v4.w * s * rsqrtf(v4.w * v4.w * var1 + EPS_) + (c4.w - mu3) * inv3;
    *reinterpret_cast<float4*>(&Y[m * D_ + 4 * tid]) = out;
}

// ---------------------------------------------------------------------------
extern "C" void kernel_launch(void* const* d_in, const int* in_sizes, int n_in,
                              void* d_out, int out_size)
{
    const float* X    = (const float*)d_in[0];
    const float* Win  = (const float*)d_in[1];
    const float* Wout = (const float*)d_in[2];
    const float* Wb   = (const float*)d_in[3];
    float* Y = (float*)d_out;

    cudaFuncSetAttribute(gemm3_f16,
                         cudaFuncAttributeMaxDynamicSharedMemorySize, GSMEM);

    split_kernel<<<(TOT16 + 255) / 256, 256>>>(X, Win, Wout, Wb);
    gemm3_f16<<<dim3(MTOK / BM, NTOT / BN), 256, GSMEM>>>();
    finalize_kernel<<<MTOK, 128>>>(X, Y);
}